// round 1
// baseline (speedup 1.0000x reference)
#include <cuda_runtime.h>
#include <math.h>

#define BATCH 32768
#define FEAT 784
#define NT 4
#define FV 196
#define NITER 8

// ---------------- scratch (device globals; no allocation allowed) ----------
__device__ __align__(16) float g_h[(size_t)BATCH * FEAT];
__device__ __align__(16) float g_q[(size_t)BATCH * FEAT];
__device__ __align__(16) float g_k[(size_t)BATCH * FEAT];
__device__ __align__(16) float g_u[(size_t)BATCH * FEAT];
__device__ __align__(16) float g_t[(size_t)BATCH * FEAT];

// ---------------------------------------------------------------------------
// GEMM specialized for N=K=196:  C[M,196] = A[M,196] @ W[196,196]^T + bias
// BM=64 rows per block, full 196 cols. 224 threads = 28 col-groups x 8 row-groups.
// micro-tile: TM=8 x TN=7. BK=14 (196 = 14*14).
// ---------------------------------------------------------------------------
__global__ __launch_bounds__(224, 2)
void gemm196_kernel(const float* __restrict__ A, const float* __restrict__ W,
                    const float* __restrict__ bias, float* __restrict__ C)
{
    __shared__ __align__(16) float As[14][64];
    __shared__ __align__(16) float Ws[14][200];   // 196 cols (+4 pad)

    const int t  = threadIdx.x;
    const int tx = t % 28;          // column group: cols tx*7 .. tx*7+6
    const int ty = t / 28;          // row group: rows ty*8 .. ty*8+7
    const int m0 = blockIdx.x * 64;

    float acc[8][7];
#pragma unroll
    for (int i = 0; i < 8; i++)
#pragma unroll
        for (int j = 0; j < 7; j++) acc[i][j] = 0.f;

    for (int k0 = 0; k0 < 196; k0 += 14) {
        // A tile: 64x14 = 896 elems, 4 per thread
#pragma unroll
        for (int i = 0; i < 4; i++) {
            int idx = t + i * 224;
            int r = idx / 14, c = idx % 14;
            As[c][r] = A[(size_t)(m0 + r) * 196 + k0 + c];
        }
        // W tile: Ws[c][n] = W[n*196 + k0 + c]; 196*14 = 2744 elems
#pragma unroll
        for (int i = 0; i < 13; i++) {
            int idx = t + i * 224;
            if (idx < 2744) {
                int n = idx / 14, c = idx % 14;
                Ws[c][n] = W[(size_t)n * 196 + k0 + c];
            }
        }
        __syncthreads();
#pragma unroll
        for (int k = 0; k < 14; k++) {
            float a[8], w[7];
            float4 a0 = *(const float4*)&As[k][ty * 8];
            float4 a1 = *(const float4*)&As[k][ty * 8 + 4];
            a[0]=a0.x; a[1]=a0.y; a[2]=a0.z; a[3]=a0.w;
            a[4]=a1.x; a[5]=a1.y; a[6]=a1.z; a[7]=a1.w;
#pragma unroll
            for (int j = 0; j < 7; j++) w[j] = Ws[k][tx * 7 + j];
#pragma unroll
            for (int i = 0; i < 8; i++)
#pragma unroll
                for (int j = 0; j < 7; j++)
                    acc[i][j] = fmaf(a[i], w[j], acc[i][j]);
        }
        __syncthreads();
    }

#pragma unroll
    for (int i = 0; i < 8; i++) {
        float* crow = C + (size_t)(m0 + ty * 8 + i) * 196 + tx * 7;
#pragma unroll
        for (int j = 0; j < 7; j++)
            crow[j] = acc[i][j] + bias[tx * 7 + j];
    }
}

// ---------------------------------------------------------------------------
// GEMM for N=K=784:  C[M,784] = A[M,784] @ W[784,784]^T + bias (optional relu)
// tile BM=128, BN=112, BK=14 (784 = 56*14, 112*7 = 784).
// 224 threads: tx in [0,14) (TN=8), ty in [0,16) (TM=8).
// ---------------------------------------------------------------------------
__global__ __launch_bounds__(224, 2)
void gemm784_kernel(const float* __restrict__ A, const float* __restrict__ W,
                    const float* __restrict__ bias, float* __restrict__ C,
                    int relu)
{
    __shared__ __align__(16) float As[14][128];
    __shared__ __align__(16) float Ws[14][112];

    const int t  = threadIdx.x;
    const int tx = t % 14;
    const int ty = t / 14;
    const int m0 = blockIdx.y * 128;
    const int n0 = blockIdx.x * 112;

    float acc[8][8];
#pragma unroll
    for (int i = 0; i < 8; i++)
#pragma unroll
        for (int j = 0; j < 8; j++) acc[i][j] = 0.f;

    for (int k0 = 0; k0 < 784; k0 += 14) {
        // A tile: 128x14 = 1792 elems, 8 per thread
#pragma unroll
        for (int i = 0; i < 8; i++) {
            int idx = t + i * 224;
            int r = idx / 14, c = idx % 14;
            As[c][r] = A[(size_t)(m0 + r) * 784 + k0 + c];
        }
        // W tile: 112x14 = 1568 elems, 7 per thread
#pragma unroll
        for (int i = 0; i < 7; i++) {
            int idx = t + i * 224;
            int n = idx / 14, c = idx % 14;
            Ws[c][n] = W[(size_t)(n0 + n) * 784 + k0 + c];
        }
        __syncthreads();
#pragma unroll
        for (int k = 0; k < 14; k++) {
            float a[8], w[8];
            float4 a0 = *(const float4*)&As[k][ty * 8];
            float4 a1 = *(const float4*)&As[k][ty * 8 + 4];
            a[0]=a0.x; a[1]=a0.y; a[2]=a0.z; a[3]=a0.w;
            a[4]=a1.x; a[5]=a1.y; a[6]=a1.z; a[7]=a1.w;
            float4 w0 = *(const float4*)&Ws[k][tx * 8];
            float4 w1 = *(const float4*)&Ws[k][tx * 8 + 4];
            w[0]=w0.x; w[1]=w0.y; w[2]=w0.z; w[3]=w0.w;
            w[4]=w1.x; w[5]=w1.y; w[6]=w1.z; w[7]=w1.w;
#pragma unroll
            for (int i = 0; i < 8; i++)
#pragma unroll
                for (int j = 0; j < 8; j++)
                    acc[i][j] = fmaf(a[i], w[j], acc[i][j]);
        }
        __syncthreads();
    }

#pragma unroll
    for (int i = 0; i < 8; i++) {
        float* crow = C + (size_t)(m0 + ty * 8 + i) * 784 + n0 + tx * 8;
#pragma unroll
        for (int j = 0; j < 8; j++) {
            float v = acc[i][j] + bias[n0 + tx * 8 + j];
            if (relu) v = fmaxf(v, 0.f);
            crow[j] = v;
        }
    }
}

// ---------------------------------------------------------------------------
// Per-batch 4x4 attention: scores = q k^T, softmax over s, h = probs @ u.
// One warp per batch element. blockDim = (32, 8).
// ---------------------------------------------------------------------------
__global__ __launch_bounds__(256)
void attn_kernel(const float* __restrict__ q, const float* __restrict__ k,
                 const float* __restrict__ u, float* __restrict__ h)
{
    const int b    = blockIdx.x * 8 + threadIdx.y;
    const int lane = threadIdx.x;
    const float* qb = q + (size_t)b * FEAT;
    const float* kb = k + (size_t)b * FEAT;
    const float* ub = u + (size_t)b * FEAT;
    float*       hb = h + (size_t)b * FEAT;

    float s[4][4];
#pragma unroll
    for (int t = 0; t < 4; t++)
#pragma unroll
        for (int r = 0; r < 4; r++) s[t][r] = 0.f;

    for (int f = lane; f < FV; f += 32) {
        float qa[4], ka[4];
#pragma unroll
        for (int t = 0; t < 4; t++) { qa[t] = qb[t * FV + f]; ka[t] = kb[t * FV + f]; }
#pragma unroll
        for (int t = 0; t < 4; t++)
#pragma unroll
            for (int r = 0; r < 4; r++)
                s[t][r] = fmaf(qa[t], ka[r], s[t][r]);
    }
    // butterfly all-reduce: every lane gets full sums
#pragma unroll
    for (int t = 0; t < 4; t++)
#pragma unroll
        for (int r = 0; r < 4; r++)
#pragma unroll
            for (int off = 16; off > 0; off >>= 1)
                s[t][r] += __shfl_xor_sync(0xffffffffu, s[t][r], off);

    float p[4][4];
#pragma unroll
    for (int t = 0; t < 4; t++) {
        float m = fmaxf(fmaxf(s[t][0], s[t][1]), fmaxf(s[t][2], s[t][3]));
        float e0 = expf(s[t][0] - m), e1 = expf(s[t][1] - m);
        float e2 = expf(s[t][2] - m), e3 = expf(s[t][3] - m);
        float inv = 1.f / (e0 + e1 + e2 + e3);
        p[t][0] = e0 * inv; p[t][1] = e1 * inv; p[t][2] = e2 * inv; p[t][3] = e3 * inv;
    }

    for (int f = lane; f < FV; f += 32) {
        float ua[4];
#pragma unroll
        for (int r = 0; r < 4; r++) ua[r] = ub[r * FV + f];
#pragma unroll
        for (int t = 0; t < 4; t++) {
            float o = 0.f;
#pragma unroll
            for (int r = 0; r < 4; r++) o = fmaf(p[t][r], ua[r], o);
            hb[t * FV + f] = o;
        }
    }
}

// ---------------------------------------------------------------------------
// Head: out[b,:] = softmax(dec[b,:] @ Wo^T + bo). One warp per row.
// ---------------------------------------------------------------------------
__global__ __launch_bounds__(256)
void head_kernel(const float* __restrict__ A, const float* __restrict__ Wo,
                 const float* __restrict__ bo, float* __restrict__ out)
{
    const int b    = blockIdx.x * 8 + threadIdx.y;
    const int lane = threadIdx.x;
    const float* a = A + (size_t)b * FEAT;

    float acc[10];
#pragma unroll
    for (int j = 0; j < 10; j++) acc[j] = 0.f;

    for (int kk = lane; kk < FEAT; kk += 32) {
        float av = a[kk];
#pragma unroll
        for (int j = 0; j < 10; j++)
            acc[j] = fmaf(av, Wo[j * FEAT + kk], acc[j]);
    }
#pragma unroll
    for (int j = 0; j < 10; j++)
#pragma unroll
        for (int off = 16; off > 0; off >>= 1)
            acc[j] += __shfl_xor_sync(0xffffffffu, acc[j], off);

    if (lane == 0) {
        float v[10], m = -1e30f;
#pragma unroll
        for (int j = 0; j < 10; j++) { v[j] = acc[j] + bo[j]; m = fmaxf(m, v[j]); }
        float ssum = 0.f;
#pragma unroll
        for (int j = 0; j < 10; j++) { v[j] = expf(v[j] - m); ssum += v[j]; }
        float inv = 1.f / ssum;
#pragma unroll
        for (int j = 0; j < 10; j++) out[(size_t)b * 10 + j] = v[j] * inv;
    }
}

// ---------------------------------------------------------------------------
extern "C" void kernel_launch(void* const* d_in, const int* in_sizes, int n_in,
                              void* d_out, int out_size)
{
    const float* x   = (const float*)d_in[0];
    const float* W1  = (const float*)d_in[1];
    const float* b1  = (const float*)d_in[2];
    const float* W2  = (const float*)d_in[3];
    const float* b2  = (const float*)d_in[4];
    const float* W3  = (const float*)d_in[5];
    const float* b3  = (const float*)d_in[6];
    const float* Wd1 = (const float*)d_in[7];
    const float* bd1 = (const float*)d_in[8];
    const float* Wd2 = (const float*)d_in[9];
    const float* bd2 = (const float*)d_in[10];
    const float* Wo  = (const float*)d_in[11];
    const float* bo  = (const float*)d_in[12];
    float* out = (float*)d_out;

    float *h, *q, *k, *u, *tmp;
    cudaGetSymbolAddress((void**)&h,   g_h);
    cudaGetSymbolAddress((void**)&q,   g_q);
    cudaGetSymbolAddress((void**)&k,   g_k);
    cudaGetSymbolAddress((void**)&u,   g_u);
    cudaGetSymbolAddress((void**)&tmp, g_t);

    cudaMemcpyAsync(h, x, (size_t)BATCH * FEAT * sizeof(float),
                    cudaMemcpyDeviceToDevice);

    const int gemm196_grid = (BATCH * NT) / 64;   // 2048 blocks of 64 rows
    for (int it = 0; it < NITER; it++) {
        gemm196_kernel<<<gemm196_grid, 224>>>(h, W1, b1, q);
        gemm196_kernel<<<gemm196_grid, 224>>>(h, W2, b2, k);
        gemm196_kernel<<<gemm196_grid, 224>>>(h, W3, b3, u);
        attn_kernel<<<BATCH / 8, dim3(32, 8)>>>(q, k, u, h);
    }

    gemm784_kernel<<<dim3(7, BATCH / 128), 224>>>(h,   Wd1, bd1, tmp, 1);
    gemm784_kernel<<<dim3(7, BATCH / 128), 224>>>(tmp, Wd2, bd2, q,   0);
    head_kernel<<<BATCH / 8, dim3(32, 8)>>>(q, Wo, bo, out);
}

// round 3
// speedup vs baseline: 2.6086x; 2.6086x over previous
#include <cuda_runtime.h>
#include <cuda_fp16.h>
#include <math.h>
#include <stdint.h>

#define BATCH 32768
#define FEAT  784
#define FV    196
#define NITER 8
#define BROWS (BATCH * 4)        // 131072 capsule rows

#define KPAD_CAP 208             // capsule K padded (13*16)
#define NPAD_CAP 224             // capsule N padded (2*112)

// ----------------------------- scratch ------------------------------------
__device__ __align__(256) __half g_hhi[(size_t)BROWS * KPAD_CAP];
__device__ __align__(256) __half g_hlo[(size_t)BROWS * KPAD_CAP];
__device__ __align__(256) float  g_q[(size_t)BROWS * FV];
__device__ __align__(256) float  g_k[(size_t)BROWS * FV];
__device__ __align__(256) float  g_u[(size_t)BROWS * FV];
__device__ __align__(256) __half g_w1hi[NPAD_CAP * KPAD_CAP], g_w1lo[NPAD_CAP * KPAD_CAP];
__device__ __align__(256) __half g_w2hi[NPAD_CAP * KPAD_CAP], g_w2lo[NPAD_CAP * KPAD_CAP];
__device__ __align__(256) __half g_w3hi[NPAD_CAP * KPAD_CAP], g_w3lo[NPAD_CAP * KPAD_CAP];
__device__ __align__(256) __half g_wd1hi[FEAT * FEAT], g_wd1lo[FEAT * FEAT];
__device__ __align__(256) __half g_wd2hi[FEAT * FEAT], g_wd2lo[FEAT * FEAT];
__device__ __align__(256) __half g_dhi[(size_t)BATCH * FEAT], g_dlo[(size_t)BATCH * FEAT];
__device__ __align__(256) __half g_thi[(size_t)BATCH * FEAT], g_tlo[(size_t)BATCH * FEAT];
__device__ __align__(256) float  g_dec[(size_t)BATCH * FEAT];

// ----------------------------- PTX helpers --------------------------------
__device__ __forceinline__ uint32_t smem_u32(const void* p) {
    uint32_t a;
    asm("{ .reg .u64 t; cvta.to.shared.u64 t, %1; cvt.u32.u64 %0, t; }" : "=r"(a) : "l"(p));
    return a;
}
__device__ __forceinline__ void cp_async16(uint32_t dst, const void* src) {
    asm volatile("cp.async.cg.shared.global [%0], [%1], 16;" :: "r"(dst), "l"(src));
}
__device__ __forceinline__ void cp_commit_wait() {
    asm volatile("cp.async.commit_group;");
    asm volatile("cp.async.wait_group 0;");
}
__device__ __forceinline__ void ldsm_x4(uint32_t* r, uint32_t addr) {
    asm volatile("ldmatrix.sync.aligned.m8n8.x4.shared.b16 {%0,%1,%2,%3}, [%4];"
                 : "=r"(r[0]), "=r"(r[1]), "=r"(r[2]), "=r"(r[3]) : "r"(addr));
}
__device__ __forceinline__ void ldsm_x2(uint32_t* r, uint32_t addr) {
    asm volatile("ldmatrix.sync.aligned.m8n8.x2.shared.b16 {%0,%1}, [%2];"
                 : "=r"(r[0]), "=r"(r[1]) : "r"(addr));
}
__device__ __forceinline__ void mma16816(float* c, const uint32_t* a, const uint32_t* b) {
    asm volatile("mma.sync.aligned.m16n8k16.row.col.f32.f16.f16.f32 "
                 "{%0,%1,%2,%3}, {%4,%5,%6,%7}, {%8,%9}, {%0,%1,%2,%3};"
                 : "+f"(c[0]), "+f"(c[1]), "+f"(c[2]), "+f"(c[3])
                 : "r"(a[0]), "r"(a[1]), "r"(a[2]), "r"(a[3]), "r"(b[0]), "r"(b[1]));
}

// ----------------------------- GEMM (fp16x3 mma.sync) ---------------------
// C[M, n_real] = (Ahi+Alo) @ (Whi+Wlo)^T + bias, fp32 accumulation.
// block: 128 x 112, K chunks of 64. 8 warps in 4x2, warp tile 32x56.
#define OFF_AHI 0u
#define OFF_ALO 16384u
#define OFF_WHI 32768u
#define OFF_WLO 47104u
#define SMEM_BYTES 61440

__global__ __launch_bounds__(256, 2)
void gemm_mma(const __half* __restrict__ Ahi, const __half* __restrict__ Alo, int lda,
              const __half* __restrict__ Whi, const __half* __restrict__ Wlo, int ldw,
              const float* __restrict__ bias,
              float* __restrict__ Cf, __half* __restrict__ Chi, __half* __restrict__ Clo,
              int ldc, int K, int n_real, int relu)
{
    extern __shared__ char smem[];
    const uint32_t sb = smem_u32(smem);
    const int tid = threadIdx.x;
    const int lane = tid & 31;
    const int wid = tid >> 5;
    const int wm = wid & 3;          // 0..3 -> rows wm*32
    const int wn = wid >> 2;         // 0..1 -> cols wn*56
    const int m0 = blockIdx.y * 128;
    const int n0 = blockIdx.x * 112;

    float acc[2][7][4];
#pragma unroll
    for (int i = 0; i < 2; i++)
#pragma unroll
        for (int j = 0; j < 7; j++)
#pragma unroll
            for (int v = 0; v < 4; v++) acc[i][j][v] = 0.f;

    for (int kc = 0; kc < K; kc += 64) {
        const int cur = min(64, K - kc);
        const int gcur = cur >> 3;          // 16B granules per row (8 or 2)

        if (kc > 0) __syncthreads();

        // A tiles (hi + lo)
        for (int idx = tid; idx < 128 * gcur; idx += 256) {
            int r = idx / gcur, g = idx - r * gcur;
            size_t src = (size_t)(m0 + r) * lda + kc + g * 8;
            uint32_t d = sb + OFF_AHI + (uint32_t)r * 128u + (uint32_t)((g ^ (r & 7)) << 4);
            cp_async16(d,          Ahi + src);
            cp_async16(d + 16384u, Alo + src);
        }
        // W tiles (hi + lo)
        for (int idx = tid; idx < 112 * gcur; idx += 256) {
            int r = idx / gcur, g = idx - r * gcur;
            size_t src = (size_t)(n0 + r) * ldw + kc + g * 8;
            uint32_t d = sb + OFF_WHI + (uint32_t)r * 128u + (uint32_t)((g ^ (r & 7)) << 4);
            cp_async16(d,          Whi + src);
            cp_async16(d + 14336u, Wlo + src);
        }
        cp_commit_wait();
        __syncthreads();

        const int nks = cur >> 4;
        for (int ks = 0; ks < nks; ks++) {
            uint32_t ah[2][4], al[2][4], bh[7][2], bl[7][2];
#pragma unroll
            for (int mf = 0; mf < 2; mf++) {
                int row = wm * 32 + mf * 16 + (lane & 15);
                int g = ks * 2 + (lane >> 4);
                uint32_t off = (uint32_t)row * 128u + (uint32_t)((g ^ (row & 7)) << 4);
                ldsm_x4(ah[mf], sb + OFF_AHI + off);
                ldsm_x4(al[mf], sb + OFF_ALO + off);
            }
#pragma unroll
            for (int nf = 0; nf < 7; nf++) {
                int row = wn * 56 + nf * 8 + (lane & 7);
                int g = ks * 2 + ((lane >> 3) & 1);
                uint32_t off = (uint32_t)row * 128u + (uint32_t)((g ^ (row & 7)) << 4);
                ldsm_x2(bh[nf], sb + OFF_WHI + off);
                ldsm_x2(bl[nf], sb + OFF_WLO + off);
            }
#pragma unroll
            for (int mf = 0; mf < 2; mf++)
#pragma unroll
                for (int nf = 0; nf < 7; nf++) {
                    mma16816(acc[mf][nf], ah[mf], bh[nf]);   // hi*hi
                    mma16816(acc[mf][nf], al[mf], bh[nf]);   // lo*hi
                    mma16816(acc[mf][nf], ah[mf], bl[nf]);   // hi*lo
                }
        }
    }

    // epilogue: registers -> bias(/relu) -> gmem
#pragma unroll
    for (int mf = 0; mf < 2; mf++)
#pragma unroll
        for (int nf = 0; nf < 7; nf++) {
            int r = m0 + wm * 32 + mf * 16 + (lane >> 2);
            int c = n0 + wn * 56 + nf * 8 + ((lane & 3) << 1);
#pragma unroll
            for (int half_ = 0; half_ < 2; half_++) {
                int rr = r + half_ * 8;
#pragma unroll
                for (int e = 0; e < 2; e++) {
                    int cc = c + e;
                    if (cc >= n_real) continue;
                    float v = acc[mf][nf][half_ * 2 + e] + bias[cc];
                    if (relu) v = fmaxf(v, 0.f);
                    size_t o = (size_t)rr * ldc + cc;
                    if (Cf) Cf[o] = v;
                    if (Chi) {
                        __half hi = __float2half_rn(v);
                        Chi[o] = hi;
                        Clo[o] = __float2half_rn(v - __half2float(hi));
                    }
                }
            }
        }
}

// ----------------------------- conversions --------------------------------
__global__ void convert_x_kernel(const float* __restrict__ x,
                                 __half* __restrict__ hhi, __half* __restrict__ hlo)
{
    size_t idx = (size_t)blockIdx.x * blockDim.x + threadIdx.x;
    if (idx >= (size_t)BROWS * KPAD_CAP) return;
    size_t R = idx / KPAD_CAP;
    int f = (int)(idx % KPAD_CAP);
    float v = (f < FV) ? x[R * FV + f] : 0.f;
    __half hi = __float2half_rn(v);
    hhi[idx] = hi;
    hlo[idx] = __float2half_rn(v - __half2float(hi));
}

__global__ void convert_w_kernel(const float* __restrict__ W, int rin, int cin,
                                 __half* __restrict__ hi, __half* __restrict__ lo,
                                 int rout, int cout)
{
    int idx = blockIdx.x * blockDim.x + threadIdx.x;
    if (idx >= rout * cout) return;
    int r = idx / cout, c = idx % cout;
    float v = (r < rin && c < cin) ? W[(size_t)r * cin + c] : 0.f;
    __half h = __float2half_rn(v);
    hi[idx] = h;
    lo[idx] = __float2half_rn(v - __half2float(h));
}

// ----------------------------- attention (fp32) ---------------------------
__global__ __launch_bounds__(256)
void attn_kernel(const float* __restrict__ q, const float* __restrict__ k,
                 const float* __restrict__ u,
                 __half* __restrict__ hhi, __half* __restrict__ hlo,
                 __half* __restrict__ dhi, __half* __restrict__ dlo,
                 int write_dec)
{
    const int b    = blockIdx.x * 8 + threadIdx.y;
    const int lane = threadIdx.x;
    const float* qb = q + (size_t)b * FEAT;
    const float* kb = k + (size_t)b * FEAT;
    const float* ub = u + (size_t)b * FEAT;

    float s[4][4];
#pragma unroll
    for (int t = 0; t < 4; t++)
#pragma unroll
        for (int r = 0; r < 4; r++) s[t][r] = 0.f;

    for (int f = lane; f < FV; f += 32) {
        float qa[4], ka[4];
#pragma unroll
        for (int t = 0; t < 4; t++) { qa[t] = qb[t * FV + f]; ka[t] = kb[t * FV + f]; }
#pragma unroll
        for (int t = 0; t < 4; t++)
#pragma unroll
            for (int r = 0; r < 4; r++)
                s[t][r] = fmaf(qa[t], ka[r], s[t][r]);
    }
#pragma unroll
    for (int t = 0; t < 4; t++)
#pragma unroll
        for (int r = 0; r < 4; r++)
#pragma unroll
            for (int off = 16; off > 0; off >>= 1)
                s[t][r] += __shfl_xor_sync(0xffffffffu, s[t][r], off);

    float p[4][4];
#pragma unroll
    for (int t = 0; t < 4; t++) {
        float m = fmaxf(fmaxf(s[t][0], s[t][1]), fmaxf(s[t][2], s[t][3]));
        float e0 = expf(s[t][0] - m), e1 = expf(s[t][1] - m);
        float e2 = expf(s[t][2] - m), e3 = expf(s[t][3] - m);
        float inv = 1.f / (e0 + e1 + e2 + e3);
        p[t][0] = e0 * inv; p[t][1] = e1 * inv; p[t][2] = e2 * inv; p[t][3] = e3 * inv;
    }

    for (int f = lane; f < FV; f += 32) {
        float ua[4];
#pragma unroll
        for (int r = 0; r < 4; r++) ua[r] = ub[r * FV + f];
#pragma unroll
        for (int t = 0; t < 4; t++) {
            float o = 0.f;
#pragma unroll
            for (int r = 0; r < 4; r++) o = fmaf(p[t][r], ua[r], o);
            __half hi = __float2half_rn(o);
            __half lo = __float2half_rn(o - __half2float(hi));
            size_t hrow = (size_t)(b * 4 + t) * KPAD_CAP + f;
            hhi[hrow] = hi;
            hlo[hrow] = lo;
            if (write_dec) {
                size_t di = (size_t)b * FEAT + t * FV + f;
                dhi[di] = hi;
                dlo[di] = lo;
            }
        }
    }
}

// ----------------------------- head ----------------------------------------
__global__ __launch_bounds__(256)
void head_kernel(const float* __restrict__ A, const float* __restrict__ Wo,
                 const float* __restrict__ bo, float* __restrict__ out)
{
    const int b    = blockIdx.x * 8 + threadIdx.y;
    const int lane = threadIdx.x;
    const float* a = A + (size_t)b * FEAT;

    float acc[10];
#pragma unroll
    for (int j = 0; j < 10; j++) acc[j] = 0.f;
    for (int kk = lane; kk < FEAT; kk += 32) {
        float av = a[kk];
#pragma unroll
        for (int j = 0; j < 10; j++)
            acc[j] = fmaf(av, Wo[j * FEAT + kk], acc[j]);
    }
#pragma unroll
    for (int j = 0; j < 10; j++)
#pragma unroll
        for (int off = 16; off > 0; off >>= 1)
            acc[j] += __shfl_xor_sync(0xffffffffu, acc[j], off);

    if (lane == 0) {
        float v[10], m = -1e30f;
#pragma unroll
        for (int j = 0; j < 10; j++) { v[j] = acc[j] + bo[j]; m = fmaxf(m, v[j]); }
        float ssum = 0.f;
#pragma unroll
        for (int j = 0; j < 10; j++) { v[j] = expf(v[j] - m); ssum += v[j]; }
        float inv = 1.f / ssum;
#pragma unroll
        for (int j = 0; j < 10; j++) out[(size_t)b * 10 + j] = v[j] * inv;
    }
}

// ---------------------------------------------------------------------------
extern "C" void kernel_launch(void* const* d_in, const int* in_sizes, int n_in,
                              void* d_out, int out_size)
{
    const float* x   = (const float*)d_in[0];
    const float* W1  = (const float*)d_in[1];
    const float* b1  = (const float*)d_in[2];
    const float* W2  = (const float*)d_in[3];
    const float* b2  = (const float*)d_in[4];
    const float* W3  = (const float*)d_in[5];
    const float* b3  = (const float*)d_in[6];
    const float* Wd1 = (const float*)d_in[7];
    const float* bd1 = (const float*)d_in[8];
    const float* Wd2 = (const float*)d_in[9];
    const float* bd2 = (const float*)d_in[10];
    const float* Wo  = (const float*)d_in[11];
    const float* bo  = (const float*)d_in[12];
    float* out = (float*)d_out;

    static int configured = 0;
    if (!configured) {
        cudaFuncSetAttribute(gemm_mma, cudaFuncAttributeMaxDynamicSharedMemorySize, SMEM_BYTES);
        configured = 1;
    }

    __half *hhi, *hlo, *w1hi, *w1lo, *w2hi, *w2lo, *w3hi, *w3lo;
    __half *wd1hi, *wd1lo, *wd2hi, *wd2lo, *dhi, *dlo, *thi, *tlo;
    float *q, *k, *u, *dec;
    cudaGetSymbolAddress((void**)&hhi, g_hhi);   cudaGetSymbolAddress((void**)&hlo, g_hlo);
    cudaGetSymbolAddress((void**)&q, g_q);       cudaGetSymbolAddress((void**)&k, g_k);
    cudaGetSymbolAddress((void**)&u, g_u);       cudaGetSymbolAddress((void**)&dec, g_dec);
    cudaGetSymbolAddress((void**)&w1hi, g_w1hi); cudaGetSymbolAddress((void**)&w1lo, g_w1lo);
    cudaGetSymbolAddress((void**)&w2hi, g_w2hi); cudaGetSymbolAddress((void**)&w2lo, g_w2lo);
    cudaGetSymbolAddress((void**)&w3hi, g_w3hi); cudaGetSymbolAddress((void**)&w3lo, g_w3lo);
    cudaGetSymbolAddress((void**)&wd1hi, g_wd1hi); cudaGetSymbolAddress((void**)&wd1lo, g_wd1lo);
    cudaGetSymbolAddress((void**)&wd2hi, g_wd2hi); cudaGetSymbolAddress((void**)&wd2lo, g_wd2lo);
    cudaGetSymbolAddress((void**)&dhi, g_dhi);   cudaGetSymbolAddress((void**)&dlo, g_dlo);
    cudaGetSymbolAddress((void**)&thi, g_thi);   cudaGetSymbolAddress((void**)&tlo, g_tlo);

    // conversions
    convert_x_kernel<<<(int)(((size_t)BROWS * KPAD_CAP + 255) / 256), 256>>>(x, hhi, hlo);
    int wcap = NPAD_CAP * KPAD_CAP;
    convert_w_kernel<<<(wcap + 255) / 256, 256>>>(W1, FV, FV, w1hi, w1lo, NPAD_CAP, KPAD_CAP);
    convert_w_kernel<<<(wcap + 255) / 256, 256>>>(W2, FV, FV, w2hi, w2lo, NPAD_CAP, KPAD_CAP);
    convert_w_kernel<<<(wcap + 255) / 256, 256>>>(W3, FV, FV, w3hi, w3lo, NPAD_CAP, KPAD_CAP);
    int wdec = FEAT * FEAT;
    convert_w_kernel<<<(wdec + 255) / 256, 256>>>(Wd1, FEAT, FEAT, wd1hi, wd1lo, FEAT, FEAT);
    convert_w_kernel<<<(wdec + 255) / 256, 256>>>(Wd2, FEAT, FEAT, wd2hi, wd2lo, FEAT, FEAT);

    // capsule iterations: N tiles in grid.x so同-row tiles co-run (A hits L2)
    const dim3 gcap(2, BROWS / 128);
    for (int it = 0; it < NITER; it++) {
        gemm_mma<<<gcap, 256, SMEM_BYTES>>>(hhi, hlo, KPAD_CAP, w1hi, w1lo, KPAD_CAP, b1,
                                            q, nullptr, nullptr, FV, KPAD_CAP, FV, 0);
        gemm_mma<<<gcap, 256, SMEM_BYTES>>>(hhi, hlo, KPAD_CAP, w2hi, w2lo, KPAD_CAP, b2,
                                            k, nullptr, nullptr, FV, KPAD_CAP, FV, 0);
        gemm_mma<<<gcap, 256, SMEM_BYTES>>>(hhi, hlo, KPAD_CAP, w3hi, w3lo, KPAD_CAP, b3,
                                            u, nullptr, nullptr, FV, KPAD_CAP, FV, 0);
        attn_kernel<<<BATCH / 8, dim3(32, 8)>>>(q, k, u, hhi, hlo, dhi, dlo, it == NITER - 1);
    }

    // decoder
    const dim3 gdec(7, BATCH / 128);
    gemm_mma<<<gdec, 256, SMEM_BYTES>>>(dhi, dlo, FEAT, wd1hi, wd1lo, FEAT, bd1,
                                        nullptr, thi, tlo, FEAT, FEAT, FEAT, 1);
    gemm_mma<<<gdec, 256, SMEM_BYTES>>>(thi, tlo, FEAT, wd2hi, wd2lo, FEAT, bd2,
                                        dec, nullptr, nullptr, FEAT, FEAT, FEAT, 0);
    head_kernel<<<BATCH / 8, dim3(32, 8)>>>(dec, Wo, bo, out);
}